// round 8
// baseline (speedup 1.0000x reference)
#include <cuda_runtime.h>
#include <cstdint>
#include <math.h>

#define PTS    8192
#define NB     4
#define NSETS  8                 // (batch, set): even = yhat, odd = y
#define NG     32                // 3D grid 32^3, cell 0.5
#define NCELL3 (NG * NG * NG)    // 32768 snake-ordered cells
#define GMIN   (-8.0f)
#define GINV   2.0f              // 1 / 0.5
#define PADP   64                // pad pairs each side
#define NPAIR  (PADP + PTS / 2 + PADP)   // 4224 pairs
#define NQBLK  (NSETS * 64)      // 512 search blocks

// Pair-packed cell-sorted points: pair j = two float4:
//   g_pp[2j]   = {x0,x1,y0,y1}   g_pp[2j+1] = {z0,z1,s0,s1}  (s = |p|^2)
// Loaded as ulonglong2 -> f32x2 operands directly. Pads: s = 3e38.
__device__ float4 g_pp[NSETS][NPAIR * 2];
__device__ float4 g_q[NSETS][PTS];           // cell-sorted queries (x,y,z,|q|^2)
__device__ int    g_hist[NSETS][NCELL3];
__device__ int    g_start[NSETS][NCELL3 + 4]; // [NCELL3] = PTS sentinel
__device__ float  g_part[NQBLK];

// 3D snake id: continuous boustrophedon over (bz, by, bx)
__device__ __forceinline__ int snake_id(int bx, int by, int bz) {
    int iy = (bz & 1) ? (NG - 1 - by) : by;
    int ix = ((by + bz) & 1) ? (NG - 1 - bx) : bx;
    return (bz * NG + iy) * NG + ix;
}
__device__ __forceinline__ int cell_of(float x, float y, float z) {
    int bx = (int)fminf(fmaxf((x - GMIN) * GINV, 0.f), (float)(NG - 1));
    int by = (int)fminf(fmaxf((y - GMIN) * GINV, 0.f), (float)(NG - 1));
    int bz = (int)fminf(fmaxf((z - GMIN) * GINV, 0.f), (float)(NG - 1));
    return snake_id(bx, by, bz);
}

#define FMA_F32X2(d, a, b, c) \
    asm("fma.rn.f32x2 %0, %1, %2, %3;" : "=l"(d) : "l"(a), "l"(b), "l"(c))
#define UNPACK_F32X2(lo, hi, v) \
    asm("mov.b64 {%0, %1}, %2;" : "=f"(lo), "=f"(hi) : "l"(v))
__device__ __forceinline__ unsigned long long pack2f(float lo, float hi) {
    unsigned long long r;
    asm("mov.b64 %0, {%1, %2};" : "=l"(r) : "f"(lo), "f"(hi));
    return r;
}

// ---------------------------------------------------------------------------
__global__ void zero_kernel() {
    int i = blockIdx.x * blockDim.x + threadIdx.x;   // 262144
    ((int*)g_hist)[i] = 0;
}

// 128 blocks x 512 : one point per thread, count snake cells
__global__ __launch_bounds__(512)
void hist_kernel(const float* __restrict__ yhat, const float* __restrict__ y)
{
    int gid = blockIdx.x * 512 + threadIdx.x;     // 0..65535
    int g = gid >> 13, i = gid & 8191;
    const float* src = ((g & 1) ? y : yhat) + (size_t)(g >> 1) * PTS * 3;
    float x = src[3 * i], yy = src[3 * i + 1], z = src[3 * i + 2];
    atomicAdd(&g_hist[g][cell_of(x, yy, z)], 1);
}

// 8 blocks (one per set) x 1024 : exclusive scan of 32768 cells (smem
// cursors, 128KB dynamic smem), write g_start + pads, then scatter this
// set's 8192 points into pair-packed snake order. Within-cell order is
// nondeterministic (atomics); final exact-min output is order-independent.
__global__ __launch_bounds__(1024)
void scanscatter_kernel(const float* __restrict__ yhat, const float* __restrict__ y)
{
    extern __shared__ int cursor[];          // NCELL3 ints
    __shared__ int wsum[32];
    const int g = blockIdx.x, t = threadIdx.x;
    const float* src = ((g & 1) ? y : yhat) + (size_t)(g >> 1) * PTS * 3;
    const int4* h4 = (const int4*)&g_hist[g][0];
    const int base4 = t * 8;                 // 8 int4 = 32 cells per thread

    int tot = 0;
#pragma unroll
    for (int j = 0; j < 8; ++j) {
        int4 v = h4[base4 + j];
        tot += v.x + v.y + v.z + v.w;
    }
    const int lane = t & 31, warp = t >> 5;
    int inc = tot;
#pragma unroll
    for (int o = 1; o < 32; o <<= 1) {
        int u = __shfl_up_sync(0xffffffffu, inc, o);
        if (lane >= o) inc += u;
    }
    if (lane == 31) wsum[warp] = inc;
    __syncthreads();
    if (warp == 0) {
        int wv = wsum[lane];
#pragma unroll
        for (int o = 1; o < 32; o <<= 1) {
            int u = __shfl_up_sync(0xffffffffu, wv, o);
            if (lane >= o) wv += u;
        }
        wsum[lane] = wv;
    }
    __syncthreads();
    int run = inc - tot + ((warp > 0) ? wsum[warp - 1] : 0);

    int4* s4 = (int4*)&g_start[g][0];
#pragma unroll
    for (int j = 0; j < 8; ++j) {
        int4 v = h4[base4 + j];
        int4 o;
        o.x = run; o.y = run + v.x; o.z = o.y + v.y; o.w = o.z + v.z;
        run = o.w + v.w;
        s4[base4 + j] = o;
        ((int4*)cursor)[base4 + j] = o;
    }
    if (t == 0) g_start[g][NCELL3] = PTS;
    if (t < PADP) {
        g_pp[g][2 * t]     = make_float4(0.f, 0.f, 0.f, 0.f);
        g_pp[g][2 * t + 1] = make_float4(0.f, 0.f, 3.0e38f, 3.0e38f);
        int o = PADP + PTS / 2 + t;
        g_pp[g][2 * o]     = make_float4(0.f, 0.f, 0.f, 0.f);
        g_pp[g][2 * o + 1] = make_float4(0.f, 0.f, 3.0e38f, 3.0e38f);
    }
    __syncthreads();

    // scatter (8 points per thread)
#pragma unroll
    for (int k = 0; k < 8; ++k) {
        int i = k * 1024 + t;
        float x = src[3 * i], yy = src[3 * i + 1], z = src[3 * i + 2];
        int pos = atomicAdd(&cursor[cell_of(x, yy, z)], 1);
        float s = x * x + yy * yy + z * z;
        int pj = PADP + (pos >> 1), sl = pos & 1;
        float* pA = (float*)&g_pp[g][2 * pj];
        pA[sl]     = x;
        pA[2 + sl] = yy;
        pA[4 + sl] = z;
        pA[6 + sl] = s;
        g_q[g][pos] = make_float4(x, yy, z, s);
    }
}

// ---------------------------------------------------------------------------
// search: warp-cooperative exact NN, 3D snake-cell pruning, vote-free.
//   bestm = min over p of (|p|^2 - 2 q.p);  d^2 = bestm + |q|^2 (clamped).
//   Phase 1: fixed 32 pairs (64 pts) around warp's anchor-cell start.
//   Window:  r = sqrt(max-lane clamp(best+|q|^2,0)); 3D cell box from lane
//            min/max coords +- r — any excluded point has per-axis gap > r
//            >= sqrt(lane best) for every lane, so it cannot win. Exact.
//   Phase 2: per (bz,by) contiguous snake runs, warp-uniform, no votes.
//   Rescans (overlap / pair rounding) harmless: idempotent min.
// ---------------------------------------------------------------------------
__global__ __launch_bounds__(128)
void search_kernel()
{
    const int bid = blockIdx.x;
    const int grp = bid >> 6;       // (b,set) 0..7
    const int sub = bid & 63;
    const int qset = grp;
    const int pset = grp ^ 1;

    const int t = threadIdx.x, warp = t >> 5, lane = t & 31;
    const int qi = (sub * 4 + warp) * 32 + lane;

    float4 q = __ldg(&g_q[qset][qi]);
    const float qx = q.x, qy = q.y, qz = q.z, sqq = q.w;
    const unsigned long long q2x = pack2f(-2.f * qx, -2.f * qx);
    const unsigned long long q2y = pack2f(-2.f * qy, -2.f * qy);
    const unsigned long long q2z = pack2f(-2.f * qz, -2.f * qz);

    // anchor cell from lane 16 (queries are snake-coherent)
    float cx = __shfl_sync(0xffffffffu, qx, 16);
    float cy = __shfl_sync(0xffffffffu, qy, 16);
    float cz = __shfl_sync(0xffffffffu, qz, 16);
    const int k0p = PADP + (__ldg(&g_start[pset][cell_of(cx, cy, cz)]) >> 1);

    float bestA = 3.0e38f, bestB = 3.0e38f;
    const ulonglong2* pp = (const ulonglong2*)&g_pp[pset][0];

#define PROC_PAIR(jj) do {                                                \
        int _j = (jj);                                                    \
        ulonglong2 v0 = __ldg(pp + 2 * _j);   /* (x0,x1)(y0,y1) */        \
        ulonglong2 v1 = __ldg(pp + 2 * _j + 1); /* (z0,z1)(s0,s1) */      \
        unsigned long long d;                                             \
        FMA_F32X2(d, q2z, v1.x, v1.y);                                    \
        FMA_F32X2(d, q2y, v0.y, d);                                       \
        FMA_F32X2(d, q2x, v0.x, d);                                       \
        float lo, hi;                                                     \
        UNPACK_F32X2(lo, hi, d);                                          \
        bestA = fminf(bestA, lo);                                         \
        bestB = fminf(bestB, hi);                                         \
    } while (0)

    // ---- phase 1: fixed 32 pairs around anchor ----
#pragma unroll
    for (int jj = 0; jj < 32; ++jj) PROC_PAIR(k0p - 8 + jj);

    // ---- window from phase-1 best ----
    float r2 = fmaxf(fminf(bestA, bestB) + sqq, 0.f);
    float xmn = qx, xmx = qx, ymn = qy, ymx = qy, zmn = qz, zmx = qz;
#pragma unroll
    for (int o = 16; o > 0; o >>= 1) {
        r2  = fmaxf(r2,  __shfl_xor_sync(0xffffffffu, r2,  o));
        xmn = fminf(xmn, __shfl_xor_sync(0xffffffffu, xmn, o));
        xmx = fmaxf(xmx, __shfl_xor_sync(0xffffffffu, xmx, o));
        ymn = fminf(ymn, __shfl_xor_sync(0xffffffffu, ymn, o));
        ymx = fmaxf(ymx, __shfl_xor_sync(0xffffffffu, ymx, o));
        zmn = fminf(zmn, __shfl_xor_sync(0xffffffffu, zmn, o));
        zmx = fmaxf(zmx, __shfl_xor_sync(0xffffffffu, zmx, o));
    }
    float r = sqrtf(r2);
    int bx0 = (int)fminf(fmaxf((xmn - r - GMIN) * GINV, 0.f), (float)(NG - 1));
    int bx1 = (int)fminf(fmaxf((xmx + r - GMIN) * GINV, 0.f), (float)(NG - 1));
    int by0 = (int)fminf(fmaxf((ymn - r - GMIN) * GINV, 0.f), (float)(NG - 1));
    int by1 = (int)fminf(fmaxf((ymx + r - GMIN) * GINV, 0.f), (float)(NG - 1));
    int bz0 = (int)fminf(fmaxf((zmn - r - GMIN) * GINV, 0.f), (float)(NG - 1));
    int bz1 = (int)fminf(fmaxf((zmx + r - GMIN) * GINV, 0.f), (float)(NG - 1));

    // ---- phase 2: snake row runs over the 3D cell box (warp-uniform) ----
    for (int bz = bz0; bz <= bz1; ++bz) {
        for (int by = by0; by <= by1; ++by) {
            int iy  = (bz & 1) ? (NG - 1 - by) : by;
            int dir = (by + bz) & 1;
            int ic0 = dir ? (NG - 1 - bx1) : bx0;
            int ic1 = dir ? (NG - 1 - bx0) : bx1;
            int rowbase = (bz * NG + iy) * NG;
            int is = __ldg(&g_start[pset][rowbase + ic0]);
            int ie = __ldg(&g_start[pset][rowbase + ic1 + 1]);
            int jp0 = PADP + (is >> 1);
            int jp1 = PADP + ((ie + 1) >> 1);
#pragma unroll 4
            for (int j = jp0; j < jp1; ++j) PROC_PAIR(j);
        }
    }

    float best = fmaxf(fminf(bestA, bestB) + sqq, 0.f);

    // block sum of mins
#pragma unroll
    for (int o = 16; o > 0; o >>= 1)
        best += __shfl_down_sync(0xffffffffu, best, o);
    __shared__ float bsum[4];
    if (lane == 0) bsum[warp] = best;
    __syncthreads();
    if (t == 0)
        g_part[bid] = bsum[0] + bsum[1] + bsum[2] + bsum[3];
}

// loss = sum(all 2*B*PTS mins) / (B*PTS);  out = sqrt(0.5 * loss)
__global__ void final_kernel(float* __restrict__ out)
{
    const int t = threadIdx.x;   // 512
    double s = (double)g_part[t];
#pragma unroll
    for (int o = 16; o > 0; o >>= 1)
        s += __shfl_down_sync(0xffffffffu, s, o);
    __shared__ double sh[16];
    if ((t & 31) == 0) sh[t >> 5] = s;
    __syncthreads();
    if (t == 0) {
        double tot = 0.0;
#pragma unroll
        for (int w = 0; w < 16; ++w) tot += sh[w];
        out[0] = (float)sqrt(0.5 * tot / (double)(NB * PTS));
    }
}

extern "C" void kernel_launch(void* const* d_in, const int* in_sizes, int n_in,
                              void* d_out, int out_size)
{
    const float* yhat = (const float*)d_in[0];   // [B, N, 3]
    const float* y    = (const float*)d_in[1];   // [B, M, 3]
    (void)in_sizes; (void)n_in; (void)out_size;

    cudaFuncSetAttribute(scanscatter_kernel,
                         cudaFuncAttributeMaxDynamicSharedMemorySize,
                         NCELL3 * (int)sizeof(int));

    zero_kernel<<<256, 1024>>>();
    hist_kernel<<<128, 512>>>(yhat, y);
    scanscatter_kernel<<<NSETS, 1024, NCELL3 * sizeof(int)>>>(yhat, y);
    search_kernel<<<NQBLK, 128>>>();
    final_kernel<<<1, 512>>>((float*)d_out);
}

// round 9
// speedup vs baseline: 1.0682x; 1.0682x over previous
#include <cuda_runtime.h>
#include <cstdint>
#include <math.h>

#define PTS    8192
#define NB     4
#define NSETS  8                 // (batch, set): even = yhat, odd = y
#define NG     64                // 3D grid 64^3, cell 0.25
#define NCELL3 (NG * NG * NG)    // 262144 snake-ordered cells
#define GMIN   (-8.0f)
#define GINV   4.0f              // 1 / 0.25
#define PADP   64                // pad pairs each side
#define NPAIR  (PADP + PTS / 2 + PADP)   // 4224 pairs
#define NQBLK  128               // search blocks (512 thr, 16 warps)

// Pair-packed cell-sorted points: pair j = two float4:
//   g_pp[2j] = {x0,x1,y0,y1}   g_pp[2j+1] = {z0,z1,s0,s1}  (s = |p|^2)
// Loaded as ulonglong2 -> f32x2 operands directly. Pads: s = 3e38.
__device__ float4 g_pp[NSETS][NPAIR * 2];
__device__ float4 g_q[NSETS][PTS];            // cell-sorted queries (x,y,z,|q|^2)
__device__ int    g_hist[NSETS][NCELL3];
__device__ int    g_start[NSETS][NCELL3 + 4]; // [NCELL3] = PTS sentinel
__device__ int    g_cur[NSETS][NCELL3];
__device__ int    g_bsum[NSETS * 64];
__device__ float  g_part[NQBLK];

// 3D snake id: continuous boustrophedon over (bz, iy, ix)
__device__ __forceinline__ int snake_id(int bx, int by, int bz) {
    int iy = (bz & 1) ? (NG - 1 - by) : by;
    int ix = ((by + bz) & 1) ? (NG - 1 - bx) : bx;
    return (bz * NG + iy) * NG + ix;
}
__device__ __forceinline__ int cell_of(float x, float y, float z) {
    int bx = (int)fminf(fmaxf((x - GMIN) * GINV, 0.f), (float)(NG - 1));
    int by = (int)fminf(fmaxf((y - GMIN) * GINV, 0.f), (float)(NG - 1));
    int bz = (int)fminf(fmaxf((z - GMIN) * GINV, 0.f), (float)(NG - 1));
    return snake_id(bx, by, bz);
}

#define FMA_F32X2(d, a, b, c) \
    asm("fma.rn.f32x2 %0, %1, %2, %3;" : "=l"(d) : "l"(a), "l"(b), "l"(c))
#define UNPACK_F32X2(lo, hi, v) \
    asm("mov.b64 {%0, %1}, %2;" : "=f"(lo), "=f"(hi) : "l"(v))
__device__ __forceinline__ unsigned long long pack2f(float lo, float hi) {
    unsigned long long r;
    asm("mov.b64 %0, {%1, %2};" : "=l"(r) : "f"(lo), "f"(hi));
    return r;
}

// ---------------------------------------------------------------------------
__global__ void zero_kernel() {   // 2M ints
    int i = blockIdx.x * blockDim.x + threadIdx.x;
    ((int*)g_hist)[i] = 0;
}

// 128 blocks x 512 : one point per thread, count snake cells
__global__ __launch_bounds__(512)
void hist_kernel(const float* __restrict__ yhat, const float* __restrict__ y)
{
    int gid = blockIdx.x * 512 + threadIdx.x;     // 0..65535
    int g = gid >> 13, i = gid & 8191;
    const float* src = ((g & 1) ? y : yhat) + (size_t)(g >> 1) * PTS * 3;
    float x = src[3 * i], yy = src[3 * i + 1], z = src[3 * i + 2];
    atomicAdd(&g_hist[g][cell_of(x, yy, z)], 1);
}

// scan level 1: 512 blocks (8 sets x 64 slices of 4096 cells). Block-exclusive
// scan of its slice into g_start (no global offset yet); slice total -> g_bsum.
__global__ __launch_bounds__(512)
void scan1_kernel()
{
    __shared__ int wsum[16];
    const int blk = blockIdx.x, s = blk >> 6, slice = blk & 63;
    const int t = threadIdx.x, lane = t & 31, warp = t >> 5;
    const int4* h4 = (const int4*)&g_hist[s][slice * 4096];
    int4 a = h4[2 * t], b = h4[2 * t + 1];
    int tot = a.x + a.y + a.z + a.w + b.x + b.y + b.z + b.w;
    int inc = tot;
#pragma unroll
    for (int o = 1; o < 32; o <<= 1) {
        int u = __shfl_up_sync(0xffffffffu, inc, o);
        if (lane >= o) inc += u;
    }
    if (lane == 31) wsum[warp] = inc;
    __syncthreads();
    if (warp == 0) {
        int wv = (lane < 16) ? wsum[lane] : 0;
#pragma unroll
        for (int o = 1; o < 16; o <<= 1) {
            int u = __shfl_up_sync(0xffffffffu, wv, o);
            if (lane >= o) wv += u;
        }
        if (lane < 16) wsum[lane] = wv;
    }
    __syncthreads();
    int run = inc - tot + ((warp > 0) ? wsum[warp - 1] : 0);
    int4 o1, o2;
    o1.x = run;          o1.y = run + a.x;   o1.z = o1.y + a.y; o1.w = o1.z + a.z;
    run = o1.w + a.w;
    o2.x = run;          o2.y = run + b.x;   o2.z = o2.y + b.y; o2.w = o2.z + b.z;
    run = o2.w + b.w;
    int4* s4 = (int4*)&g_start[s][slice * 4096];
    s4[2 * t] = o1; s4[2 * t + 1] = o2;
    if (t == 511) g_bsum[blk] = run;
}

// scan level 2 + fixup: add per-slice global offset, init cursors, pads,
// sentinel.
__global__ __launch_bounds__(512)
void scan2_kernel()
{
    __shared__ int sh[64];
    const int blk = blockIdx.x, s = blk >> 6, slice = blk & 63;
    const int t = threadIdx.x;
    if (t < 64) sh[t] = g_bsum[(s << 6) + t];
    __syncthreads();
    int off = 0;
    for (int i = 0; i < slice; ++i) off += sh[i];
    int4* s4 = (int4*)&g_start[s][slice * 4096];
    int4* c4 = (int4*)&g_cur[s][slice * 4096];
    int4 a = s4[2 * t], b = s4[2 * t + 1];
    a.x += off; a.y += off; a.z += off; a.w += off;
    b.x += off; b.y += off; b.z += off; b.w += off;
    s4[2 * t] = a; c4[2 * t] = a;
    s4[2 * t + 1] = b; c4[2 * t + 1] = b;
    if (slice == 63 && t == 511) g_start[s][NCELL3] = PTS;
    if (slice == 0 && t < PADP) {
        g_pp[s][2 * t]     = make_float4(0.f, 0.f, 0.f, 0.f);
        g_pp[s][2 * t + 1] = make_float4(0.f, 0.f, 3.0e38f, 3.0e38f);
        int o = PADP + PTS / 2 + t;
        g_pp[s][2 * o]     = make_float4(0.f, 0.f, 0.f, 0.f);
        g_pp[s][2 * o + 1] = make_float4(0.f, 0.f, 3.0e38f, 3.0e38f);
    }
}

// 128 blocks x 512 : scatter points into pair-packed snake order.
// Within-cell order is nondeterministic (atomics); final exact-min output is
// order-independent (fminf is exactly associative/commutative).
__global__ __launch_bounds__(512)
void scatter_kernel(const float* __restrict__ yhat, const float* __restrict__ y)
{
    int gid = blockIdx.x * 512 + threadIdx.x;
    int g = gid >> 13, i = gid & 8191;
    const float* src = ((g & 1) ? y : yhat) + (size_t)(g >> 1) * PTS * 3;
    float x = src[3 * i], yy = src[3 * i + 1], z = src[3 * i + 2];
    int pos = atomicAdd(&g_cur[g][cell_of(x, yy, z)], 1);
    float s = x * x + yy * yy + z * z;
    int pj = PADP + (pos >> 1), sl = pos & 1;
    float* pA = (float*)&g_pp[g][2 * pj];
    pA[sl]     = x;
    pA[2 + sl] = yy;
    pA[4 + sl] = z;
    pA[6 + sl] = s;
    g_q[g][pos] = make_float4(x, yy, z, s);
}

// ---------------------------------------------------------------------------
// search: warp-cooperative exact NN, 3D snake-cell pruning, vote-free.
//   bestm = min over p of (|p|^2 - 2 q.p);  d^2 = bestm + |q|^2 (clamped).
//   Phase 1: fixed 32 pairs (64 pts) around warp's anchor-cell start.
//   Box: per-lane radius r_l = sqrt(clamp(best_l+|q_l|^2,0)); box =
//        [min_l(c_l - r_l), max_l(c_l + r_l)] per axis. Any point improving
//        lane l lies within r_l of q_l per-axis -> inside box. Exact.
//   Phase 2: lanes prefetch up to 32 row bounds in parallel (full MLP),
//        then warp consumes rows; pair loop overshoots to x4 (extra pairs
//        are real candidates or 3e38-pads -> harmless, idempotent min).
// ---------------------------------------------------------------------------
__global__ __launch_bounds__(512)
void search_kernel()
{
    __shared__ int2 rowb[512];     // [warp][lane]
    __shared__ float bsum[16];

    const int bid = blockIdx.x;
    const int grp = bid >> 4;      // (b,set) 0..7
    const int sub = bid & 15;
    const int qset = grp;
    const int pset = grp ^ 1;

    const int t = threadIdx.x, warp = t >> 5, lane = t & 31;
    const int qi = (sub * 16 + warp) * 32 + lane;

    float4 q = __ldg(&g_q[qset][qi]);
    const float qx = q.x, qy = q.y, qz = q.z, sqq = q.w;
    const unsigned long long q2x = pack2f(-2.f * qx, -2.f * qx);
    const unsigned long long q2y = pack2f(-2.f * qy, -2.f * qy);
    const unsigned long long q2z = pack2f(-2.f * qz, -2.f * qz);

    // anchor cell from lane 16 (queries are snake-coherent)
    float cx = __shfl_sync(0xffffffffu, qx, 16);
    float cy = __shfl_sync(0xffffffffu, qy, 16);
    float cz = __shfl_sync(0xffffffffu, qz, 16);
    const int k0p = PADP + (__ldg(&g_start[pset][cell_of(cx, cy, cz)]) >> 1);

    float bestA = 3.0e38f, bestB = 3.0e38f;
    const ulonglong2* pp = (const ulonglong2*)&g_pp[pset][0];

#define PROC_PAIR(jj) do {                                                \
        int _j = (jj);                                                    \
        ulonglong2 v0 = __ldg(pp + 2 * _j);     /* (x0,x1)(y0,y1) */      \
        ulonglong2 v1 = __ldg(pp + 2 * _j + 1); /* (z0,z1)(s0,s1) */      \
        unsigned long long d;                                             \
        FMA_F32X2(d, q2z, v1.x, v1.y);                                    \
        FMA_F32X2(d, q2y, v0.y, d);                                       \
        FMA_F32X2(d, q2x, v0.x, d);                                       \
        float lo, hi;                                                     \
        UNPACK_F32X2(lo, hi, d);                                          \
        bestA = fminf(bestA, lo);                                         \
        bestB = fminf(bestB, hi);                                         \
    } while (0)

    // ---- phase 1: fixed 32 pairs around anchor ----
#pragma unroll
    for (int jj = 0; jj < 32; ++jj) PROC_PAIR(k0p - 8 + jj);

    // ---- per-lane-radius box ----
    float rl = sqrtf(fmaxf(fminf(bestA, bestB) + sqq, 0.f));
    float xmn = qx - rl, xmx = qx + rl;
    float ymn = qy - rl, ymx = qy + rl;
    float zmn = qz - rl, zmx = qz + rl;
#pragma unroll
    for (int o = 16; o > 0; o >>= 1) {
        xmn = fminf(xmn, __shfl_xor_sync(0xffffffffu, xmn, o));
        xmx = fmaxf(xmx, __shfl_xor_sync(0xffffffffu, xmx, o));
        ymn = fminf(ymn, __shfl_xor_sync(0xffffffffu, ymn, o));
        ymx = fmaxf(ymx, __shfl_xor_sync(0xffffffffu, ymx, o));
        zmn = fminf(zmn, __shfl_xor_sync(0xffffffffu, zmn, o));
        zmx = fmaxf(zmx, __shfl_xor_sync(0xffffffffu, zmx, o));
    }
    int bx0 = (int)fminf(fmaxf((xmn - GMIN) * GINV, 0.f), (float)(NG - 1));
    int bx1 = (int)fminf(fmaxf((xmx - GMIN) * GINV, 0.f), (float)(NG - 1));
    int by0 = (int)fminf(fmaxf((ymn - GMIN) * GINV, 0.f), (float)(NG - 1));
    int by1 = (int)fminf(fmaxf((ymx - GMIN) * GINV, 0.f), (float)(NG - 1));
    int bz0 = (int)fminf(fmaxf((zmn - GMIN) * GINV, 0.f), (float)(NG - 1));
    int bz1 = (int)fminf(fmaxf((zmx - GMIN) * GINV, 0.f), (float)(NG - 1));

    // ---- phase 2: chunked parallel row-bounds prefetch + consume ----
    const int NYb = by1 - by0 + 1;
    const int NR  = NYb * (bz1 - bz0 + 1);
    for (int cb = 0; cb < NR; cb += 32) {
        int ri = cb + lane;
        int2 bnd = make_int2(0, 0);
        if (ri < NR) {
            int by = by0 + ri % NYb;
            int bz = bz0 + ri / NYb;
            int iy  = (bz & 1) ? (NG - 1 - by) : by;
            int dir = (by + bz) & 1;
            int ic0 = dir ? (NG - 1 - bx1) : bx0;
            int ic1 = dir ? (NG - 1 - bx0) : bx1;
            int rowbase = (bz * NG + iy) * NG;
            int is = __ldg(&g_start[pset][rowbase + ic0]);
            int ie = __ldg(&g_start[pset][rowbase + ic1 + 1]);
            bnd = make_int2(PADP + (is >> 1), PADP + ((ie + 1) >> 1));
        }
        rowb[warp * 32 + lane] = bnd;
        __syncwarp();
        int nrows = min(32, NR - cb);
        for (int rr = 0; rr < nrows; ++rr) {
            int2 b = rowb[warp * 32 + rr];
            for (int j = b.x; j < b.y; j += 4) {   // overshoot <=3 pairs: safe
                PROC_PAIR(j);
                PROC_PAIR(j + 1);
                PROC_PAIR(j + 2);
                PROC_PAIR(j + 3);
            }
        }
        __syncwarp();
    }

    float best = fmaxf(fminf(bestA, bestB) + sqq, 0.f);

    // block sum of mins
#pragma unroll
    for (int o = 16; o > 0; o >>= 1)
        best += __shfl_down_sync(0xffffffffu, best, o);
    if (lane == 0) bsum[warp] = best;
    __syncthreads();
    if (t == 0) {
        float s = 0.f;
#pragma unroll
        for (int w = 0; w < 16; ++w) s += bsum[w];
        g_part[bid] = s;
    }
}

// loss = sum(all 2*B*PTS mins) / (B*PTS);  out = sqrt(0.5 * loss)
__global__ void final_kernel(float* __restrict__ out)
{
    const int t = threadIdx.x;   // 128
    double s = (double)g_part[t];
#pragma unroll
    for (int o = 16; o > 0; o >>= 1)
        s += __shfl_down_sync(0xffffffffu, s, o);
    __shared__ double sh[4];
    if ((t & 31) == 0) sh[t >> 5] = s;
    __syncthreads();
    if (t == 0) {
        double tot = sh[0] + sh[1] + sh[2] + sh[3];
        out[0] = (float)sqrt(0.5 * tot / (double)(NB * PTS));
    }
}

extern "C" void kernel_launch(void* const* d_in, const int* in_sizes, int n_in,
                              void* d_out, int out_size)
{
    const float* yhat = (const float*)d_in[0];   // [B, N, 3]
    const float* y    = (const float*)d_in[1];   // [B, M, 3]
    (void)in_sizes; (void)n_in; (void)out_size;

    zero_kernel<<<2048, 1024>>>();
    hist_kernel<<<128, 512>>>(yhat, y);
    scan1_kernel<<<512, 512>>>();
    scan2_kernel<<<512, 512>>>();
    scatter_kernel<<<128, 512>>>(yhat, y);
    search_kernel<<<NQBLK, 512>>>();       // launch #6: ncu -s 5 captures this
    final_kernel<<<1, 128>>>((float*)d_out);
}

// round 10
// speedup vs baseline: 1.5966x; 1.4946x over previous
#include <cuda_runtime.h>
#include <cstdint>
#include <math.h>

#define PTS    8192
#define NB     4
#define NSETS  8                 // (batch, set): even = yhat, odd = y
#define NG     64                // 3D grid 64^3, cell 0.25
#define NCELL3 (NG * NG * NG)    // 262144 snake-ordered cells
#define GMIN   (-8.0f)
#define GINV   4.0f
#define PADP   64                // pad pairs each side
#define NPAIR  (PADP + PTS / 2 + PADP)   // 4224 pairs
#define NQBLK  128               // search blocks (512 thr, 16 warps)
#define NRMAX  32                // light/heavy row threshold

__device__ float4 g_pp[NSETS][NPAIR * 2];     // pair-packed: {x0x1,y0y1},{z0z1,s0s1}
__device__ float4 g_q[NSETS][PTS];            // cell-sorted queries (x,y,z,|q|^2)
__device__ int    g_hist[NSETS][NCELL3];
__device__ int    g_start[NSETS][NCELL3 + 4]; // [NCELL3] = PTS sentinel
__device__ int    g_cur[NSETS][NCELL3];
__device__ int    g_bsum[NSETS * 64];
__device__ float  g_res[NSETS][PTS];          // per-query min d^2 (clamped)
__device__ int    g_heavy[NSETS * PTS];       // heavy query codes
__device__ int    g_hcount;
__device__ float  g_part[64];

__device__ __forceinline__ int snake_id(int bx, int by, int bz) {
    int iy = (bz & 1) ? (NG - 1 - by) : by;
    int ix = ((by + bz) & 1) ? (NG - 1 - bx) : bx;
    return (bz * NG + iy) * NG + ix;
}
__device__ __forceinline__ int cell_of(float x, float y, float z) {
    int bx = (int)fminf(fmaxf((x - GMIN) * GINV, 0.f), (float)(NG - 1));
    int by = (int)fminf(fmaxf((y - GMIN) * GINV, 0.f), (float)(NG - 1));
    int bz = (int)fminf(fmaxf((z - GMIN) * GINV, 0.f), (float)(NG - 1));
    return snake_id(bx, by, bz);
}

#define FMA_F32X2(d, a, b, c) \
    asm("fma.rn.f32x2 %0, %1, %2, %3;" : "=l"(d) : "l"(a), "l"(b), "l"(c))
#define UNPACK_F32X2(lo, hi, v) \
    asm("mov.b64 {%0, %1}, %2;" : "=f"(lo), "=f"(hi) : "l"(v))
__device__ __forceinline__ unsigned long long pack2f(float lo, float hi) {
    unsigned long long r;
    asm("mov.b64 %0, {%1, %2};" : "=l"(r) : "f"(lo), "f"(hi));
    return r;
}

// d^2 partial for one packed pair: bestA/B accumulate (|p|^2 - 2 q.p)
__device__ __forceinline__ void proc_pair(
    const ulonglong2* __restrict__ pp, int j,
    unsigned long long q2x, unsigned long long q2y, unsigned long long q2z,
    float& bestA, float& bestB)
{
    ulonglong2 v0 = __ldg(pp + 2 * j);       // (x0,x1)(y0,y1)
    ulonglong2 v1 = __ldg(pp + 2 * j + 1);   // (z0,z1)(s0,s1)
    unsigned long long d;
    FMA_F32X2(d, q2z, v1.x, v1.y);
    FMA_F32X2(d, q2y, v0.y, d);
    FMA_F32X2(d, q2x, v0.x, d);
    float lo, hi;
    UNPACK_F32X2(lo, hi, d);
    bestA = fminf(bestA, lo);
    bestB = fminf(bestB, hi);
}

// ---------------------------------------------------------------------------
__global__ void zero_kernel() {   // zero g_hist (2M ints) + g_hcount
    int i = blockIdx.x * blockDim.x + threadIdx.x;
    ((int*)g_hist)[i] = 0;
    if (i == 0) g_hcount = 0;
}

__global__ __launch_bounds__(512)
void hist_kernel(const float* __restrict__ yhat, const float* __restrict__ y)
{
    int gid = blockIdx.x * 512 + threadIdx.x;
    int g = gid >> 13, i = gid & 8191;
    const float* src = ((g & 1) ? y : yhat) + (size_t)(g >> 1) * PTS * 3;
    float x = src[3 * i], yy = src[3 * i + 1], z = src[3 * i + 2];
    atomicAdd(&g_hist[g][cell_of(x, yy, z)], 1);
}

// scan level 1: 512 blocks (8 sets x 64 slices of 4096). Slice-local scan.
__global__ __launch_bounds__(512)
void scan1_kernel()
{
    __shared__ int wsum[16];
    const int blk = blockIdx.x, s = blk >> 6, slice = blk & 63;
    const int t = threadIdx.x, lane = t & 31, warp = t >> 5;
    const int4* h4 = (const int4*)&g_hist[s][slice * 4096];
    int4 a = h4[2 * t], b = h4[2 * t + 1];
    int tot = a.x + a.y + a.z + a.w + b.x + b.y + b.z + b.w;
    int inc = tot;
#pragma unroll
    for (int o = 1; o < 32; o <<= 1) {
        int u = __shfl_up_sync(0xffffffffu, inc, o);
        if (lane >= o) inc += u;
    }
    if (lane == 31) wsum[warp] = inc;
    __syncthreads();
    if (warp == 0) {
        int wv = (lane < 16) ? wsum[lane] : 0;
#pragma unroll
        for (int o = 1; o < 16; o <<= 1) {
            int u = __shfl_up_sync(0xffffffffu, wv, o);
            if (lane >= o) wv += u;
        }
        if (lane < 16) wsum[lane] = wv;
    }
    __syncthreads();
    int run = inc - tot + ((warp > 0) ? wsum[warp - 1] : 0);
    int4 o1, o2;
    o1.x = run;        o1.y = run + a.x;  o1.z = o1.y + a.y; o1.w = o1.z + a.z;
    run = o1.w + a.w;
    o2.x = run;        o2.y = run + b.x;  o2.z = o2.y + b.y; o2.w = o2.z + b.z;
    run = o2.w + b.w;
    int4* s4 = (int4*)&g_start[s][slice * 4096];
    s4[2 * t] = o1; s4[2 * t + 1] = o2;
    if (t == 511) g_bsum[blk] = run;
}

// scan level 2 + fixup: add per-slice offsets, init cursors, pads, sentinel.
__global__ __launch_bounds__(512)
void scan2_kernel()
{
    __shared__ int sh[64];
    const int blk = blockIdx.x, s = blk >> 6, slice = blk & 63;
    const int t = threadIdx.x;
    if (t < 64) sh[t] = g_bsum[(s << 6) + t];
    __syncthreads();
    int off = 0;
    for (int i = 0; i < slice; ++i) off += sh[i];
    int4* s4 = (int4*)&g_start[s][slice * 4096];
    int4* c4 = (int4*)&g_cur[s][slice * 4096];
    int4 a = s4[2 * t], b = s4[2 * t + 1];
    a.x += off; a.y += off; a.z += off; a.w += off;
    b.x += off; b.y += off; b.z += off; b.w += off;
    s4[2 * t] = a; c4[2 * t] = a;
    s4[2 * t + 1] = b; c4[2 * t + 1] = b;
    if (slice == 63 && t == 511) g_start[s][NCELL3] = PTS;
    if (slice == 0 && t < PADP) {
        g_pp[s][2 * t]     = make_float4(0.f, 0.f, 0.f, 0.f);
        g_pp[s][2 * t + 1] = make_float4(0.f, 0.f, 3.0e38f, 3.0e38f);
        int o = PADP + PTS / 2 + t;
        g_pp[s][2 * o]     = make_float4(0.f, 0.f, 0.f, 0.f);
        g_pp[s][2 * o + 1] = make_float4(0.f, 0.f, 3.0e38f, 3.0e38f);
    }
}

// scatter into pair-packed snake order (within-cell order nondeterministic;
// exact-min output is order-independent).
__global__ __launch_bounds__(512)
void scatter_kernel(const float* __restrict__ yhat, const float* __restrict__ y)
{
    int gid = blockIdx.x * 512 + threadIdx.x;
    int g = gid >> 13, i = gid & 8191;
    const float* src = ((g & 1) ? y : yhat) + (size_t)(g >> 1) * PTS * 3;
    float x = src[3 * i], yy = src[3 * i + 1], z = src[3 * i + 2];
    int pos = atomicAdd(&g_cur[g][cell_of(x, yy, z)], 1);
    float s = x * x + yy * yy + z * z;
    int pj = PADP + (pos >> 1), sl = pos & 1;
    float* pA = (float*)&g_pp[g][2 * pj];
    pA[sl]     = x;
    pA[2 + sl] = yy;
    pA[4 + sl] = z;
    pA[6 + sl] = s;
    g_q[g][pos] = make_float4(x, yy, z, s);
}

// ---------------------------------------------------------------------------
// search: phase 1 (64 snake-adjacent points) -> per-lane radius box.
// NR <= NRMAX rows: broadcast row scan (light). Else: defer to heavy_kernel
// (full lane-strided scan), which bounds straggler cost. Both exact.
// ---------------------------------------------------------------------------
__global__ __launch_bounds__(512)
void search_kernel()
{
    __shared__ int2 rowb[512];

    const int bid = blockIdx.x;
    const int grp = bid >> 4;      // (b,set) 0..7
    const int sub = bid & 15;
    const int qset = grp;
    const int pset = grp ^ 1;

    const int t = threadIdx.x, warp = t >> 5, lane = t & 31;
    const int qi = (sub * 16 + warp) * 32 + lane;

    float4 q = __ldg(&g_q[qset][qi]);
    const float qx = q.x, qy = q.y, qz = q.z, sqq = q.w;
    const unsigned long long q2x = pack2f(-2.f * qx, -2.f * qx);
    const unsigned long long q2y = pack2f(-2.f * qy, -2.f * qy);
    const unsigned long long q2z = pack2f(-2.f * qz, -2.f * qz);

    float cx = __shfl_sync(0xffffffffu, qx, 16);
    float cy = __shfl_sync(0xffffffffu, qy, 16);
    float cz = __shfl_sync(0xffffffffu, qz, 16);
    const int k0p = PADP + (__ldg(&g_start[pset][cell_of(cx, cy, cz)]) >> 1);

    float bestA = 3.0e38f, bestB = 3.0e38f;
    const ulonglong2* pp = (const ulonglong2*)&g_pp[pset][0];

    // phase 1: fixed 32 pairs around anchor
#pragma unroll
    for (int jj = 0; jj < 32; ++jj)
        proc_pair(pp, k0p - 8 + jj, q2x, q2y, q2z, bestA, bestB);

    // per-lane-radius box (exact: improving point for lane l is within r_l
    // of q_l on every axis)
    float rl = sqrtf(fmaxf(fminf(bestA, bestB) + sqq, 0.f));
    float xmn = qx - rl, xmx = qx + rl;
    float ymn = qy - rl, ymx = qy + rl;
    float zmn = qz - rl, zmx = qz + rl;
#pragma unroll
    for (int o = 16; o > 0; o >>= 1) {
        xmn = fminf(xmn, __shfl_xor_sync(0xffffffffu, xmn, o));
        xmx = fmaxf(xmx, __shfl_xor_sync(0xffffffffu, xmx, o));
        ymn = fminf(ymn, __shfl_xor_sync(0xffffffffu, ymn, o));
        ymx = fmaxf(ymx, __shfl_xor_sync(0xffffffffu, ymx, o));
        zmn = fminf(zmn, __shfl_xor_sync(0xffffffffu, zmn, o));
        zmx = fmaxf(zmx, __shfl_xor_sync(0xffffffffu, zmx, o));
    }
    int bx0 = (int)fminf(fmaxf((xmn - GMIN) * GINV, 0.f), (float)(NG - 1));
    int bx1 = (int)fminf(fmaxf((xmx - GMIN) * GINV, 0.f), (float)(NG - 1));
    int by0 = (int)fminf(fmaxf((ymn - GMIN) * GINV, 0.f), (float)(NG - 1));
    int by1 = (int)fminf(fmaxf((ymx - GMIN) * GINV, 0.f), (float)(NG - 1));
    int bz0 = (int)fminf(fmaxf((zmn - GMIN) * GINV, 0.f), (float)(NG - 1));
    int bz1 = (int)fminf(fmaxf((zmx - GMIN) * GINV, 0.f), (float)(NG - 1));

    const int NYb = by1 - by0 + 1;
    const int NR  = NYb * (bz1 - bz0 + 1);

    if (NR > NRMAX) {
        // heavy: whole warp defers its 32 queries
        int base;
        if (lane == 0) base = atomicAdd(&g_hcount, 32);
        base = __shfl_sync(0xffffffffu, base, 0);
        g_heavy[base + lane] = (qset << 16) | qi;
        return;
    }

    // light: single-chunk parallel row-bounds prefetch + broadcast consume
    int2 bnd = make_int2(0, 0);
    if (lane < NR) {
        int by = by0 + lane % NYb;
        int bz = bz0 + lane / NYb;
        int iy  = (bz & 1) ? (NG - 1 - by) : by;
        int dir = (by + bz) & 1;
        int ic0 = dir ? (NG - 1 - bx1) : bx0;
        int ic1 = dir ? (NG - 1 - bx0) : bx1;
        int rowbase = (bz * NG + iy) * NG;
        int is = __ldg(&g_start[pset][rowbase + ic0]);
        int ie = __ldg(&g_start[pset][rowbase + ic1 + 1]);
        bnd = make_int2(PADP + (is >> 1), PADP + ((ie + 1) >> 1));
    }
    rowb[warp * 32 + lane] = bnd;
    __syncwarp();
    for (int rr = 0; rr < NR; ++rr) {
        int2 b = rowb[warp * 32 + rr];
        for (int j = b.x; j < b.y; j += 4) {   // overshoot <=3 pairs: safe
            proc_pair(pp, j,     q2x, q2y, q2z, bestA, bestB);
            proc_pair(pp, j + 1, q2x, q2y, q2z, bestA, bestB);
            proc_pair(pp, j + 2, q2x, q2y, q2z, bestA, bestB);
            proc_pair(pp, j + 3, q2x, q2y, q2z, bestA, bestB);
        }
    }

    g_res[qset][qi] = fmaxf(fminf(bestA, bestB) + sqq, 0.f);
}

// heavy: one warp per deferred query; lanes stride the full pair array
// (coalesced), butterfly-min. 128 iterations/lane.
__global__ __launch_bounds__(256)
void heavy_kernel()
{
    const int gw = (blockIdx.x * 256 + threadIdx.x) >> 5;
    const int lane = threadIdx.x & 31;
    const int nw = (gridDim.x * 256) >> 5;
    const int H = g_hcount;

    for (int h = gw; h < H; h += nw) {
        int code = g_heavy[h];
        int qset = code >> 16, qi = code & 0xffff, pset = qset ^ 1;
        float4 q = __ldg(&g_q[qset][qi]);
        const unsigned long long q2x = pack2f(-2.f * q.x, -2.f * q.x);
        const unsigned long long q2y = pack2f(-2.f * q.y, -2.f * q.y);
        const unsigned long long q2z = pack2f(-2.f * q.z, -2.f * q.z);
        const ulonglong2* pp = (const ulonglong2*)&g_pp[pset][0];

        float bestA = 3.0e38f, bestB = 3.0e38f;
#pragma unroll 4
        for (int j = PADP + lane; j < PADP + PTS / 2; j += 32)
            proc_pair(pp, j, q2x, q2y, q2z, bestA, bestB);

        float best = fminf(bestA, bestB);
#pragma unroll
        for (int o = 16; o > 0; o >>= 1)
            best = fminf(best, __shfl_xor_sync(0xffffffffu, best, o));
        if (lane == 0)
            g_res[qset][qi] = fmaxf(best + q.w, 0.f);
    }
}

// 2-stage sum of 65536 per-query mins
__global__ void reduce_partial_kernel()
{
    const int t = threadIdx.x, bid = blockIdx.x;
    const float* r = (const float*)g_res;
    float s = 0.f;
#pragma unroll
    for (int k = 0; k < 4; ++k)
        s += r[bid * 1024 + k * 256 + t];
#pragma unroll
    for (int o = 16; o > 0; o >>= 1)
        s += __shfl_down_sync(0xffffffffu, s, o);
    __shared__ float sh[8];
    if ((t & 31) == 0) sh[t >> 5] = s;
    __syncthreads();
    if (t == 0) {
        float v = 0.f;
#pragma unroll
        for (int w = 0; w < 8; ++w) v += sh[w];
        g_part[bid] = v;
    }
}

__global__ void final_kernel(float* __restrict__ out)
{
    const int t = threadIdx.x;   // 32
    double s = (double)g_part[t] + (double)g_part[t + 32];
#pragma unroll
    for (int o = 16; o > 0; o >>= 1)
        s += __shfl_down_sync(0xffffffffu, s, o);
    if (t == 0)
        out[0] = (float)sqrt(0.5 * s / (double)(NB * PTS));
}

extern "C" void kernel_launch(void* const* d_in, const int* in_sizes, int n_in,
                              void* d_out, int out_size)
{
    const float* yhat = (const float*)d_in[0];   // [B, N, 3]
    const float* y    = (const float*)d_in[1];   // [B, M, 3]
    (void)in_sizes; (void)n_in; (void)out_size;

    zero_kernel<<<2048, 1024>>>();
    hist_kernel<<<128, 512>>>(yhat, y);
    scan1_kernel<<<512, 512>>>();
    scan2_kernel<<<512, 512>>>();
    scatter_kernel<<<128, 512>>>(yhat, y);
    search_kernel<<<NQBLK, 512>>>();       // 6th kernel: ncu -s 5 target
    heavy_kernel<<<296, 256>>>();
    reduce_partial_kernel<<<64, 256>>>();
    final_kernel<<<1, 32>>>((float*)d_out);
}